// round 5
// baseline (speedup 1.0000x reference)
#include <cuda_runtime.h>
#include <cuda_fp16.h>
#include <math.h>

#define DET0 128
#define DET1 128
#define VOL_ELEMS (128*128*128)
#define N_STEPS 226
#define N_RAYS (4*128*128)
#define WARPS_PER_BLOCK 8

// per-ray precomputed state: [0]=(s0,s1,s2,tmin) [1]=(d0,d1,d2,tmax) [2]=(t_in,t_out,-,-)
__device__ float4 g_ray[N_RAYS * 3];

// corner-packed fp16 volume: entry (b,x,y,z) = half4(v(y,z), v(y,z+1), v(y+1,z), v(y+1,z+1))
// stored as uint2 (8 bytes). 4 * 128^3 * 8B = 67 MB static scratch.
__device__ uint2 g_W[4 * VOL_ELEMS];

// ---------------- setup: per-ray geometry ----------------
__global__ void __launch_bounds__(256) drr_setup_kernel(
    const float* __restrict__ params)   // (4,6)
{
    const int ray = blockIdx.x * 256 + threadIdx.x;
    const int iv = ray & 127;
    const int iu = (ray >> 7) & 127;
    const int b  = ray >> 14;

    const float* p = params + b * 6;
    float sx = sinf(p[0]), cx = cosf(p[0]);
    float sy = sinf(p[1]), cy = cosf(p[1]);
    float sz = sinf(p[2]), cz = cosf(p[2]);

    float T00 = cy*cz,  T01 = cx*sz + sx*sy*cz,  T02 = sx*sz - cx*sy*cz;
    float T10 = -cy*sz, T11 = cx*cz - sx*sy*sz,  T12 = sx*cz + cx*sy*sz;
    float T20 = sy,     T21 = -sx*cy,            T22 = cx*cy;

    float tv0 = -p[3], tv1 = -p[4], tv2 = 1000.0f - p[5];
    float s0 = 64.0f - (T00*tv0 + T01*tv1 + T02*tv2);
    float s1 = 64.0f - (T10*tv0 + T11*tv1 + T12*tv2);
    float s2 = 64.0f - (T20*tv0 + T21*tv1 + T22*tv2);

    float qx = ((float)iu + 0.5f) * 0.001f - 0.064f;
    float qy = ((float)iv + 0.5f) * 0.001f - 0.064f;

    float d0 = T00*qx + T01*qy + T02;
    float d1 = T10*qx + T11*qy + T12;
    float d2 = T20*qx + T21*qy + T22;
    float nrm = sqrtf(d0*d0 + d1*d1 + d2*d2);
    d0 /= nrm; d1 /= nrm; d2 /= nrm;

    float sd0 = (fabsf(d0) < 1e-8f) ? 1e-8f : d0;
    float sd1 = (fabsf(d1) < 1e-8f) ? 1e-8f : d1;
    float sd2 = (fabsf(d2) < 1e-8f) ? 1e-8f : d2;
    float a0 = (0.0f - s0) / sd0, b0_ = (128.0f - s0) / sd0;
    float a1 = (0.0f - s1) / sd1, b1_ = (128.0f - s1) / sd1;
    float a2 = (0.0f - s2) / sd2, b2_ = (128.0f - s2) / sd2;
    float tmin = fmaxf(fmaxf(fminf(a0,b0_), fminf(a1,b1_)), fminf(a2,b2_));
    tmin = fmaxf(tmin, 0.0f);
    float tmax = fminf(fminf(fmaxf(a0,b0_), fmaxf(a1,b1_)), fmaxf(a2,b2_));

    float e0 = (0.5f - s0) / sd0, g0 = (126.5f - s0) / sd0;
    float e1 = (0.5f - s1) / sd1, g1 = (126.5f - s1) / sd1;
    float e2 = (0.5f - s2) / sd2, g2 = (126.5f - s2) / sd2;
    float t_in  = fmaxf(fmaxf(fminf(e0,g0), fminf(e1,g1)), fminf(e2,g2));
    float t_out = fminf(fminf(fmaxf(e0,g0), fmaxf(e1,g1)), fmaxf(e2,g2));

    g_ray[ray*3 + 0] = make_float4(s0, s1, s2, tmin);
    g_ray[ray*3 + 1] = make_float4(d0, d1, d2, tmax);
    g_ray[ray*3 + 2] = make_float4(t_in, t_out, 0.0f, 0.0f);
}

// ---------------- prepass: build corner-packed fp16 volume ----------------
// one thread produces W entries for z = 2t and 2t+1 at fixed (b, x, y)
__global__ void __launch_bounds__(256) drr_pack_kernel(
    const float* __restrict__ vol)
{
    const int tid = blockIdx.x * 256 + threadIdx.x;   // 4 * 128 * 128 * 64
    const int t = tid & 63;
    const int y = (tid >> 6) & 127;
    const int x = (tid >> 13) & 127;
    const int b = tid >> 20;

    const float* r0 = vol + (((size_t)(b * 128 + x)) * 128 + y) * 128;
    const float* r1 = (y < 127) ? (r0 + 128) : r0;    // y+1 clamped (unused by fast path)
    const int z0 = t * 2;

    float2 a = __ldg((const float2*)(r0 + z0));
    float2 c = __ldg((const float2*)(r1 + z0));
    float a2, c2;
    if (t < 63) {
        a2 = __ldg(r0 + z0 + 2);
        c2 = __ldg(r1 + z0 + 2);
    } else {                                          // z+1 = 128 clamped (unused)
        a2 = a.y; c2 = c.y;
    }

    __half2 e0lo = __float22half2_rn(make_float2(a.x, a.y));
    __half2 e0hi = __float22half2_rn(make_float2(c.x, c.y));
    __half2 e1lo = __float22half2_rn(make_float2(a.y, a2));
    __half2 e1hi = __float22half2_rn(make_float2(c.y, c2));

    uint4 o;
    o.x = *reinterpret_cast<unsigned*>(&e0lo);
    o.y = *reinterpret_cast<unsigned*>(&e0hi);
    o.z = *reinterpret_cast<unsigned*>(&e1lo);
    o.w = *reinterpret_cast<unsigned*>(&e1hi);

    size_t widx = (((size_t)(b * 128 + x)) * 128 + y) * 128 + z0;  // even -> 16B aligned
    *reinterpret_cast<uint4*>(&g_W[widx]) = o;
}

// ---------------- march ----------------
__global__ void __launch_bounds__(WARPS_PER_BLOCK * 32, 8) drr_march_kernel(
    const float* __restrict__ vol,      // (4,1,128,128,128) exact, boundary path
    float* __restrict__ out)            // (4,1,128,128)
{
    const int lane    = threadIdx.x & 31;
    const int warp_id = threadIdx.x >> 5;
    const int ray     = blockIdx.x * WARPS_PER_BLOCK + warp_id;
    const int b       = ray >> 14;

    const float4 A = __ldg(&g_ray[ray*3 + 0]);
    const float4 B = __ldg(&g_ray[ray*3 + 1]);
    const float4 C = __ldg(&g_ray[ray*3 + 2]);
    const float s0 = A.x, s1 = A.y, s2 = A.z, tmin = A.w;
    const float d0 = B.x, d1 = B.y, d2 = B.z, tmax = B.w;
    const float t_in = C.x, t_out = C.y;

    const float* __restrict__ v = vol + (size_t)b * VOL_ELEMS;
    const uint2* __restrict__ W = g_W + (size_t)b * VOL_ELEMS;

    const float lane_f = (float)lane + 0.5f;

    float acc = 0.0f;
    float kbase = 0.0f;
    for (int j = 0; j < (N_STEPS + 31) / 32; j++, kbase += 32.0f) {
        float tk0 = tmin + (kbase + 0.5f);
        if (tk0 >= tmax) break;               // warp-uniform

        float tk = tmin + (kbase + lane_f);   // exact reference rounding
        float u  = tmin + (kbase + 31.5f);

        bool fast = (tk0 >= t_in) && (u <= t_out) && (u < tmax) && (j < 7);

        float px = fmaf(tk, d0, s0);
        float py = fmaf(tk, d1, s1);
        float pz = fmaf(tk, d2, s2);
        float fx = floorf(px), fy = floorf(py), fz = floorf(pz);
        float rx = px - fx, ry = py - fy, rz = pz - fz;

        if (fast) {
            // indices provably in [0,126]
            float Wf = fmaf(fx, 16384.0f, fmaf(fy, 128.0f, fz));
            int r = (int)Wf;
            uint2 w0 = __ldg(W + r);
            uint2 w1 = __ldg(W + r + 16384);

            __half2 h00 = *reinterpret_cast<__half2*>(&w0.x);  // (v(y,z), v(y,z+1)) at x
            __half2 h01 = *reinterpret_cast<__half2*>(&w0.y);  // (v(y+1,z), v(y+1,z+1)) at x
            __half2 h10 = *reinterpret_cast<__half2*>(&w1.x);  // same at x+1
            __half2 h11 = *reinterpret_cast<__half2*>(&w1.y);

            float2 f00 = __half22float2(h00);
            float2 f01 = __half22float2(h01);
            float2 f10 = __half22float2(h10);
            float2 f11 = __half22float2(h11);

            float lzA = fmaf(rz, f00.y - f00.x, f00.x);
            float lzB = fmaf(rz, f01.y - f01.x, f01.x);
            float ly0 = fmaf(ry, lzB - lzA, lzA);

            float lzC = fmaf(rz, f10.y - f10.x, f10.x);
            float lzD = fmaf(rz, f11.y - f11.x, f11.x);
            float ly1 = fmaf(ry, lzD - lzC, lzC);

            acc += fmaf(rx, ly1 - ly0, ly0);
        } else {
            int ix = (int)fx, iy = (int)fy, iz = (int)fz;
            int k = (int)kbase + lane;
            bool live = (k < N_STEPS) && (tk < tmax);

            float wx0 = ((unsigned)ix       < 128u) ? (1.0f - rx) : 0.0f;
            float wx1 = ((unsigned)(ix + 1) < 128u) ? rx          : 0.0f;
            float wy0 = ((unsigned)iy       < 128u) ? (1.0f - ry) : 0.0f;
            float wy1 = ((unsigned)(iy + 1) < 128u) ? ry          : 0.0f;
            float wz0 = ((unsigned)iz       < 128u) ? (1.0f - rz) : 0.0f;
            float wz1 = ((unsigned)(iz + 1) < 128u) ? rz          : 0.0f;
            if (!live) { wz0 = 0.0f; wz1 = 0.0f; }

            int cx0 = min(max(ix,     0), 127);
            int cx1 = min(max(ix + 1, 0), 127);
            int cy0 = min(max(iy,     0), 127);
            int cy1 = min(max(iy + 1, 0), 127);
            int cz0 = min(max(iz,     0), 127);
            int cz1 = min(max(iz + 1, 0), 127);

            int r00 = cx0 * 16384 + cy0 * 128;
            int r01 = cx0 * 16384 + cy1 * 128;
            int r10 = cx1 * 16384 + cy0 * 128;
            int r11 = cx1 * 16384 + cy1 * 128;

            float v000 = __ldg(v + r00 + cz0);
            float v001 = __ldg(v + r00 + cz1);
            float v010 = __ldg(v + r01 + cz0);
            float v011 = __ldg(v + r01 + cz1);
            float v100 = __ldg(v + r10 + cz0);
            float v101 = __ldg(v + r10 + cz1);
            float v110 = __ldg(v + r11 + cz0);
            float v111 = __ldg(v + r11 + cz1);

            float w00 = wx0 * wy0;
            float w01 = wx0 * wy1;
            float w10 = wx1 * wy0;
            float w11 = wx1 * wy1;

            float sz0v = v000 * w00;
            sz0v = fmaf(v010, w01, sz0v);
            sz0v = fmaf(v100, w10, sz0v);
            sz0v = fmaf(v110, w11, sz0v);
            float sz1v = v001 * w00;
            sz1v = fmaf(v011, w01, sz1v);
            sz1v = fmaf(v101, w10, sz1v);
            sz1v = fmaf(v111, w11, sz1v);

            acc = fmaf(sz0v, wz0, acc);
            acc = fmaf(sz1v, wz1, acc);
        }
    }

    #pragma unroll
    for (int off = 16; off > 0; off >>= 1)
        acc += __shfl_xor_sync(0xFFFFFFFFu, acc, off);

    if (lane == 0)
        out[ray] = acc * 0.1f;
}

extern "C" void kernel_launch(void* const* d_in, const int* in_sizes, int n_in,
                              void* d_out, int out_size)
{
    const float* vol    = (const float*)d_in[0];
    const float* params = (const float*)d_in[1];
    float* out = (float*)d_out;

    drr_pack_kernel<<<(4 * 128 * 128 * 64) / 256, 256>>>(vol);
    drr_setup_kernel<<<N_RAYS / 256, 256>>>(params);
    drr_march_kernel<<<N_RAYS / WARPS_PER_BLOCK, WARPS_PER_BLOCK * 32>>>(vol, out);
}

// round 6
// speedup vs baseline: 1.1764x; 1.1764x over previous
#include <cuda_runtime.h>
#include <cuda_fp16.h>
#include <math.h>

#define DET0 128
#define DET1 128
#define VOL_ELEMS (128*128*128)
#define N_STEPS 226
#define N_RAYS (4*128*128)
#define WARPS_PER_BLOCK 8

// per-ray precomputed state: [0]=(s0,s1,s2,tmin) [1]=(d0,d1,d2,tmax) [2]=(t_in,t_out,-,-)
__device__ float4 g_ray[N_RAYS * 3];

// y-pair packed fp16 volume: P(b,x,y,z) = half2( v(x,y,z), v(x,y+1,z) )
// 4 bytes per voxel -> 32 MB total, same footprint as the fp32 source.
__device__ unsigned g_P[4 * VOL_ELEMS];

// ---------------- setup: per-ray geometry ----------------
__global__ void __launch_bounds__(256) drr_setup_kernel(
    const float* __restrict__ params)   // (4,6)
{
    const int ray = blockIdx.x * 256 + threadIdx.x;
    const int iv = ray & 127;
    const int iu = (ray >> 7) & 127;
    const int b  = ray >> 14;

    const float* p = params + b * 6;
    float sx = sinf(p[0]), cx = cosf(p[0]);
    float sy = sinf(p[1]), cy = cosf(p[1]);
    float sz = sinf(p[2]), cz = cosf(p[2]);

    float T00 = cy*cz,  T01 = cx*sz + sx*sy*cz,  T02 = sx*sz - cx*sy*cz;
    float T10 = -cy*sz, T11 = cx*cz - sx*sy*sz,  T12 = sx*cz + cx*sy*sz;
    float T20 = sy,     T21 = -sx*cy,            T22 = cx*cy;

    float tv0 = -p[3], tv1 = -p[4], tv2 = 1000.0f - p[5];
    float s0 = 64.0f - (T00*tv0 + T01*tv1 + T02*tv2);
    float s1 = 64.0f - (T10*tv0 + T11*tv1 + T12*tv2);
    float s2 = 64.0f - (T20*tv0 + T21*tv1 + T22*tv2);

    float qx = ((float)iu + 0.5f) * 0.001f - 0.064f;
    float qy = ((float)iv + 0.5f) * 0.001f - 0.064f;

    float d0 = T00*qx + T01*qy + T02;
    float d1 = T10*qx + T11*qy + T12;
    float d2 = T20*qx + T21*qy + T22;
    float nrm = sqrtf(d0*d0 + d1*d1 + d2*d2);
    d0 /= nrm; d1 /= nrm; d2 /= nrm;

    float sd0 = (fabsf(d0) < 1e-8f) ? 1e-8f : d0;
    float sd1 = (fabsf(d1) < 1e-8f) ? 1e-8f : d1;
    float sd2 = (fabsf(d2) < 1e-8f) ? 1e-8f : d2;
    float a0 = (0.0f - s0) / sd0, b0_ = (128.0f - s0) / sd0;
    float a1 = (0.0f - s1) / sd1, b1_ = (128.0f - s1) / sd1;
    float a2 = (0.0f - s2) / sd2, b2_ = (128.0f - s2) / sd2;
    float tmin = fmaxf(fmaxf(fminf(a0,b0_), fminf(a1,b1_)), fminf(a2,b2_));
    tmin = fmaxf(tmin, 0.0f);
    float tmax = fminf(fminf(fmaxf(a0,b0_), fmaxf(a1,b1_)), fmaxf(a2,b2_));

    float e0 = (0.5f - s0) / sd0, g0 = (126.5f - s0) / sd0;
    float e1 = (0.5f - s1) / sd1, g1 = (126.5f - s1) / sd1;
    float e2 = (0.5f - s2) / sd2, g2 = (126.5f - s2) / sd2;
    float t_in  = fmaxf(fmaxf(fminf(e0,g0), fminf(e1,g1)), fminf(e2,g2));
    float t_out = fminf(fminf(fmaxf(e0,g0), fmaxf(e1,g1)), fmaxf(e2,g2));

    g_ray[ray*3 + 0] = make_float4(s0, s1, s2, tmin);
    g_ray[ray*3 + 1] = make_float4(d0, d1, d2, tmax);
    g_ray[ray*3 + 2] = make_float4(t_in, t_out, 0.0f, 0.0f);
}

// ---------------- prepass: build y-pair packed fp16 volume ----------------
// thread handles 4 consecutive z at fixed (b, x, y): 2x float4 read, 1x uint4 write
__global__ void __launch_bounds__(256) drr_pack_kernel(
    const float* __restrict__ vol)
{
    const int tid = blockIdx.x * 256 + threadIdx.x;   // 4*128*128*32 threads
    const int zb = tid & 31;                          // z block (4 z per thread)
    const int y  = (tid >> 5) & 127;
    const int x  = (tid >> 12) & 127;
    const int b  = tid >> 19;

    const size_t row = (((size_t)(b * 128 + x)) * 128 + y) * 128;
    const int z0 = zb * 4;

    float4 a = __ldg((const float4*)(vol + row + z0));               // row y
    const float* r1 = vol + ((y < 127) ? row + 128 : row);           // row y+1 (clamp; P[127] unused by fast path)
    float4 c = __ldg((const float4*)(r1 + z0));

    __half2 h0 = __floats2half2_rn(a.x, c.x);
    __half2 h1 = __floats2half2_rn(a.y, c.y);
    __half2 h2 = __floats2half2_rn(a.z, c.z);
    __half2 h3 = __floats2half2_rn(a.w, c.w);

    uint4 o;
    o.x = *reinterpret_cast<unsigned*>(&h0);
    o.y = *reinterpret_cast<unsigned*>(&h1);
    o.z = *reinterpret_cast<unsigned*>(&h2);
    o.w = *reinterpret_cast<unsigned*>(&h3);

    *reinterpret_cast<uint4*>(&g_P[row + z0]) = o;    // z0 % 4 == 0 -> 16B aligned
}

// ---------------- march ----------------
__global__ void __launch_bounds__(WARPS_PER_BLOCK * 32, 8) drr_march_kernel(
    const float* __restrict__ vol,      // exact fp32, boundary path
    float* __restrict__ out)            // (4,1,128,128)
{
    const int lane    = threadIdx.x & 31;
    const int warp_id = threadIdx.x >> 5;
    const int ray     = blockIdx.x * WARPS_PER_BLOCK + warp_id;
    const int b       = ray >> 14;

    const float4 A = __ldg(&g_ray[ray*3 + 0]);
    const float4 B = __ldg(&g_ray[ray*3 + 1]);
    const float4 C = __ldg(&g_ray[ray*3 + 2]);
    const float s0 = A.x, s1 = A.y, s2 = A.z, tmin = A.w;
    const float d0 = B.x, d1 = B.y, d2 = B.z, tmax = B.w;
    const float t_in = C.x, t_out = C.y;

    const float*    __restrict__ v  = vol + (size_t)b * VOL_ELEMS;
    const unsigned* __restrict__ P  = g_P + (size_t)b * VOL_ELEMS;

    const float lane_f = (float)lane + 0.5f;

    float acc = 0.0f;
    float kbase = 0.0f;
    for (int j = 0; j < (N_STEPS + 31) / 32; j++, kbase += 32.0f) {
        float tk0 = tmin + (kbase + 0.5f);
        if (tk0 >= tmax) break;               // warp-uniform

        float tk = tmin + (kbase + lane_f);   // exact reference rounding
        float u  = tmin + (kbase + 31.5f);

        bool fast = (tk0 >= t_in) && (u <= t_out) && (u < tmax) && (j < 7);

        float px = fmaf(tk, d0, s0);
        float py = fmaf(tk, d1, s1);
        float pz = fmaf(tk, d2, s2);
        float fx = floorf(px), fy = floorf(py), fz = floorf(pz);
        float rx = px - fx, ry = py - fy, rz = pz - fz;

        if (fast) {
            // indices provably in [0,126]
            float Wf = fmaf(fx, 16384.0f, fmaf(fy, 128.0f, fz));
            int r = (int)Wf;
            unsigned u00 = __ldg(P + r);              // (v(y,z),   v(y+1,z))   at x
            unsigned u01 = __ldg(P + r + 1);          // (v(y,z+1), v(y+1,z+1)) at x
            unsigned u10 = __ldg(P + r + 16384);      // same at x+1
            unsigned u11 = __ldg(P + r + 16385);

            float2 f00 = __half22float2(*reinterpret_cast<__half2*>(&u00));
            float2 f01 = __half22float2(*reinterpret_cast<__half2*>(&u01));
            float2 f10 = __half22float2(*reinterpret_cast<__half2*>(&u10));
            float2 f11 = __half22float2(*reinterpret_cast<__half2*>(&u11));

            // z-lerp (componentwise over y-pair), then y, then x
            float z0a = fmaf(rz, f01.x - f00.x, f00.x);   // x,   y
            float z0b = fmaf(rz, f01.y - f00.y, f00.y);   // x,   y+1
            float z1a = fmaf(rz, f11.x - f10.x, f10.x);   // x+1, y
            float z1b = fmaf(rz, f11.y - f10.y, f10.y);   // x+1, y+1

            float ly0 = fmaf(ry, z0b - z0a, z0a);
            float ly1 = fmaf(ry, z1b - z1a, z1a);

            acc += fmaf(rx, ly1 - ly0, ly0);
        } else {
            int ix = (int)fx, iy = (int)fy, iz = (int)fz;
            int k = (int)kbase + lane;
            bool live = (k < N_STEPS) && (tk < tmax);

            float wx0 = ((unsigned)ix       < 128u) ? (1.0f - rx) : 0.0f;
            float wx1 = ((unsigned)(ix + 1) < 128u) ? rx          : 0.0f;
            float wy0 = ((unsigned)iy       < 128u) ? (1.0f - ry) : 0.0f;
            float wy1 = ((unsigned)(iy + 1) < 128u) ? ry          : 0.0f;
            float wz0 = ((unsigned)iz       < 128u) ? (1.0f - rz) : 0.0f;
            float wz1 = ((unsigned)(iz + 1) < 128u) ? rz          : 0.0f;
            if (!live) { wz0 = 0.0f; wz1 = 0.0f; }

            int cx0 = min(max(ix,     0), 127);
            int cx1 = min(max(ix + 1, 0), 127);
            int cy0 = min(max(iy,     0), 127);
            int cy1 = min(max(iy + 1, 0), 127);
            int cz0 = min(max(iz,     0), 127);
            int cz1 = min(max(iz + 1, 0), 127);

            int r00 = cx0 * 16384 + cy0 * 128;
            int r01 = cx0 * 16384 + cy1 * 128;
            int r10 = cx1 * 16384 + cy0 * 128;
            int r11 = cx1 * 16384 + cy1 * 128;

            float v000 = __ldg(v + r00 + cz0);
            float v001 = __ldg(v + r00 + cz1);
            float v010 = __ldg(v + r01 + cz0);
            float v011 = __ldg(v + r01 + cz1);
            float v100 = __ldg(v + r10 + cz0);
            float v101 = __ldg(v + r10 + cz1);
            float v110 = __ldg(v + r11 + cz0);
            float v111 = __ldg(v + r11 + cz1);

            float w00 = wx0 * wy0;
            float w01 = wx0 * wy1;
            float w10 = wx1 * wy0;
            float w11 = wx1 * wy1;

            float sz0v = v000 * w00;
            sz0v = fmaf(v010, w01, sz0v);
            sz0v = fmaf(v100, w10, sz0v);
            sz0v = fmaf(v110, w11, sz0v);
            float sz1v = v001 * w00;
            sz1v = fmaf(v011, w01, sz1v);
            sz1v = fmaf(v101, w10, sz1v);
            sz1v = fmaf(v111, w11, sz1v);

            acc = fmaf(sz0v, wz0, acc);
            acc = fmaf(sz1v, wz1, acc);
        }
    }

    #pragma unroll
    for (int off = 16; off > 0; off >>= 1)
        acc += __shfl_xor_sync(0xFFFFFFFFu, acc, off);

    if (lane == 0)
        out[ray] = acc * 0.1f;
}

extern "C" void kernel_launch(void* const* d_in, const int* in_sizes, int n_in,
                              void* d_out, int out_size)
{
    const float* vol    = (const float*)d_in[0];
    const float* params = (const float*)d_in[1];
    float* out = (float*)d_out;

    drr_pack_kernel<<<(4 * 128 * 128 * 32) / 256, 256>>>(vol);
    drr_setup_kernel<<<N_RAYS / 256, 256>>>(params);
    drr_march_kernel<<<N_RAYS / WARPS_PER_BLOCK, WARPS_PER_BLOCK * 32>>>(vol, out);
}